// round 15
// baseline (speedup 1.0000x reference)
#include <cuda_runtime.h>
#include <cuda_bf16.h>
#include <math.h>
#include <stdint.h>

#define SEQ 4096
#define DM 1024
#define NH 16
#define HS 64

// Scratch (no cudaMalloc allowed)
__device__ float g_qkv[SEQ * 3 * DM];               // [s][3*1024]
__device__ float g_attn[SEQ * DM];                  // [s][h*64+d]
__device__ __nv_bfloat16 g_Qh[NH * SEQ * HS], g_Ql[NH * SEQ * HS];  // RoPE'd, pre-scaled
__device__ __nv_bfloat16 g_Kh[NH * SEQ * HS], g_Kl[NH * SEQ * HS];  // RoPE'd
__device__ __nv_bfloat16 g_Vh[NH * SEQ * HS], g_Vl[NH * SEQ * HS];

// ===========================================================================
// Warp-MMA helpers (base ISA, compiles for plain sm_103 target)
// ===========================================================================
__device__ __forceinline__ uint32_t smem_u32(const void* p) {
    uint32_t a;
    asm("{ .reg .u64 t; cvta.to.shared.u64 t, %1; cvt.u32.u64 %0, t; }" : "=r"(a) : "l"(p));
    return a;
}
__device__ __forceinline__ void ldsm_x4(uint32_t* r, uint32_t addr) {
    asm volatile("ldmatrix.sync.aligned.m8n8.x4.shared.b16 {%0,%1,%2,%3}, [%4];"
                 : "=r"(r[0]), "=r"(r[1]), "=r"(r[2]), "=r"(r[3]) : "r"(addr));
}
__device__ __forceinline__ void ldsm_x2(uint32_t& r0, uint32_t& r1, uint32_t addr) {
    asm volatile("ldmatrix.sync.aligned.m8n8.x2.shared.b16 {%0,%1}, [%2];"
                 : "=r"(r0), "=r"(r1) : "r"(addr));
}
__device__ __forceinline__ void ldsm_x2t(uint32_t& r0, uint32_t& r1, uint32_t addr) {
    asm volatile("ldmatrix.sync.aligned.m8n8.x2.trans.shared.b16 {%0,%1}, [%2];"
                 : "=r"(r0), "=r"(r1) : "r"(addr));
}
__device__ __forceinline__ void mma16816(float* c, const uint32_t* a, uint32_t b0, uint32_t b1) {
    asm volatile("mma.sync.aligned.m16n8k16.row.col.f32.bf16.bf16.f32 "
                 "{%0,%1,%2,%3}, {%4,%5,%6,%7}, {%8,%9}, {%0,%1,%2,%3};"
                 : "+f"(c[0]), "+f"(c[1]), "+f"(c[2]), "+f"(c[3])
                 : "r"(a[0]), "r"(a[1]), "r"(a[2]), "r"(a[3]), "r"(b0), "r"(b1));
}
// split (a,b) floats into packed bf16x2 hi and residual lo (low half = a)
__device__ __forceinline__ void split2(float a, float b, uint32_t& hi, uint32_t& lo) {
    __nv_bfloat16 ha = __float2bfloat16(a), hb = __float2bfloat16(b);
    float ra = a - __bfloat162float(ha), rb = b - __bfloat162float(hb);
    __nv_bfloat16 la = __float2bfloat16(ra), lb = __float2bfloat16(rb);
    hi = (uint32_t)__bfloat16_as_ushort(ha) | ((uint32_t)__bfloat16_as_ushort(hb) << 16);
    lo = (uint32_t)__bfloat16_as_ushort(la) | ((uint32_t)__bfloat16_as_ushort(lb) << 16);
}

// ===========================================================================
// Flash attention (best-known R11 structure): smem tiles [128][64+8] bf16
// hi/lo pairs, plain uint4 loads, monolithic per-tile compute.
// ===========================================================================
#define TSTR 72
#define E_QH 0
#define E_QL 9216
#define E_KH 18432
#define E_KL 27648
#define E_VH 36864
#define E_VL 46080
#define FLASH_SMEM (55296 * 2)

__global__ __launch_bounds__(256, 1) void flash_mma() {
    extern __shared__ __nv_bfloat16 sm[];
    uint32_t sbase = smem_u32(sm);

    int tid = threadIdx.x;
    int w = tid >> 5, lane = tid & 31;
    int g = lane >> 2, t = lane & 3;
    int h = blockIdx.y;
    int i = (gridDim.x - 1) - blockIdx.x;    // long rows first

    size_t hb = (size_t)h * SEQ * HS;
    const __nv_bfloat16* Kh = g_Kh + hb;
    const __nv_bfloat16* Kl = g_Kl + hb;
    const __nv_bfloat16* Vh = g_Vh + hb;
    const __nv_bfloat16* Vl = g_Vl + hb;

    // ---- Load pre-split Q tile (hi/lo) straight into padded smem
    {
        const __nv_bfloat16* Qh = g_Qh + hb + (size_t)i * 128 * HS;
        const __nv_bfloat16* Ql = g_Ql + hb + (size_t)i * 128 * HS;
        #pragma unroll
        for (int c = 0; c < 4; c++) {
            int idx = tid + c * 256;           // 0..1023
            int r = idx >> 3, ch = (idx & 7) * 8;
            int e = r * TSTR + ch;
            *(uint4*)&sm[E_QH + e] = *(const uint4*)(Qh + r * 64 + ch);
            *(uint4*)&sm[E_QL + e] = *(const uint4*)(Ql + r * 64 + ch);
        }
    }
    __syncthreads();

    // ---- Q A-fragments (persistent): 4 k-blocks x {hi,lo}
    uint32_t qa_h[4][4], qa_l[4][4];
    {
        int arow = w * 16 + (lane & 15);
        int acol = (lane >> 4) * 8;
        #pragma unroll
        for (int kb = 0; kb < 4; kb++) {
            ldsm_x4(qa_h[kb], sbase + (uint32_t)(E_QH + arow * TSTR + kb * 16 + acol) * 2);
            ldsm_x4(qa_l[kb], sbase + (uint32_t)(E_QL + arow * TSTR + kb * 16 + acol) * 2);
        }
    }

    float o[8][4] = {};
    float lsum0 = 0.f, lsum8 = 0.f;
    int rg = i * 128 + w * 16 + g;          // global q row for c0/c1 lanes

    int kb_row = lane & 7;                  // S-gemm B rows within n-tile
    int kb_col = ((lane >> 3) & 1) * 8;     // k halves
    int v_row  = lane & 15;                 // PV B rows within k-block

    for (int j = 0; j <= i; j++) {
        __syncthreads();   // all warps done reading previous K/V
        // ---- Load pre-split K, V tiles (hi/lo) — straight copies, no convert
        size_t off = (size_t)j * 128 * HS;
        #pragma unroll
        for (int c = 0; c < 4; c++) {
            int idx = tid + c * 256;
            int r = idx >> 3, ch = (idx & 7) * 8;
            int e = r * TSTR + ch;
            size_t go = off + r * 64 + ch;
            *(uint4*)&sm[E_KH + e] = *(const uint4*)(Kh + go);
            *(uint4*)&sm[E_KL + e] = *(const uint4*)(Kl + go);
            *(uint4*)&sm[E_VH + e] = *(const uint4*)(Vh + go);
            *(uint4*)&sm[E_VL + e] = *(const uint4*)(Vl + go);
        }
        __syncthreads();

        // ---- S = Q K^T : 16 n-tiles x 4 k-blocks x 3 split passes
        float sc[16][4];
        #pragma unroll
        for (int nt = 0; nt < 16; nt++)
            #pragma unroll
            for (int e = 0; e < 4; e++) sc[nt][e] = 0.f;

        #pragma unroll
        for (int nt = 0; nt < 16; nt++) {
            int brow = nt * 8 + kb_row;
            #pragma unroll
            for (int kb = 0; kb < 4; kb++) {
                uint32_t bh0, bh1, bl0, bl1;
                ldsm_x2(bh0, bh1, sbase + (uint32_t)(E_KH + brow * TSTR + kb * 16 + kb_col) * 2);
                ldsm_x2(bl0, bl1, sbase + (uint32_t)(E_KL + brow * TSTR + kb * 16 + kb_col) * 2);
                mma16816(sc[nt], qa_h[kb], bh0, bh1);
                mma16816(sc[nt], qa_h[kb], bl0, bl1);
                mma16816(sc[nt], qa_l[kb], bh0, bh1);
            }
        }

        // ---- softmax in registers (no max subtraction) + repack C->A frags
        uint32_t ph[8][4], pl[8][4];
        #pragma unroll
        for (int nt = 0; nt < 16; nt++) {
            int cg = j * 128 + nt * 8 + 2 * t;
            float p0 = (cg     <= rg)     ? __expf(sc[nt][0]) : 0.f;
            float p1 = (cg + 1 <= rg)     ? __expf(sc[nt][1]) : 0.f;
            float p2 = (cg     <= rg + 8) ? __expf(sc[nt][2]) : 0.f;
            float p3 = (cg + 1 <= rg + 8) ? __expf(sc[nt][3]) : 0.f;
            lsum0 += p0 + p1;
            lsum8 += p2 + p3;
            int pk = nt >> 1;
            int r01 = (nt & 1) * 2;
            split2(p0, p1, ph[pk][r01],     pl[pk][r01]);
            split2(p2, p3, ph[pk][r01 + 1], pl[pk][r01 + 1]);
        }

        // ---- O += P V : 8 d-tiles x 8 k-blocks x 3 split passes (fully unrolled)
        #pragma unroll
        for (int dt = 0; dt < 8; dt++) {
            #pragma unroll
            for (int kb = 0; kb < 8; kb++) {
                uint32_t vh0, vh1, vl0, vl1;
                int vr = kb * 16 + v_row;
                ldsm_x2t(vh0, vh1, sbase + (uint32_t)(E_VH + vr * TSTR + dt * 8) * 2);
                ldsm_x2t(vl0, vl1, sbase + (uint32_t)(E_VL + vr * TSTR + dt * 8) * 2);
                mma16816(o[dt], ph[kb], vh0, vh1);
                mma16816(o[dt], ph[kb], vl0, vl1);
                mma16816(o[dt], pl[kb], vh0, vh1);
            }
        }
    }

    // ---- Epilogue: reduce row sums over quad, normalize, store fp32
    lsum0 += __shfl_xor_sync(0xffffffffu, lsum0, 1);
    lsum0 += __shfl_xor_sync(0xffffffffu, lsum0, 2);
    lsum8 += __shfl_xor_sync(0xffffffffu, lsum8, 1);
    lsum8 += __shfl_xor_sync(0xffffffffu, lsum8, 2);
    float inv0 = 1.f / lsum0, inv8 = 1.f / lsum8;

    float* d0 = g_attn + (size_t)rg * DM + h * HS + 2 * t;
    float* d8 = g_attn + (size_t)(rg + 8) * DM + h * HS + 2 * t;
    #pragma unroll
    for (int dt = 0; dt < 8; dt++) {
        *(float2*)(d0 + dt * 8) = make_float2(o[dt][0] * inv0, o[dt][1] * inv0);
        *(float2*)(d8 + dt * 8) = make_float2(o[dt][2] * inv8, o[dt][3] * inv8);
    }
}

// ---------------------------------------------------------------------------
// C[m][n] = sum_k A[m][k] * B[n][k]   (both K-major). M%128==N%128==0, K%8==0.
// (proven fp32 projection GEMM: 247us QKV / 82us O-proj)
// ---------------------------------------------------------------------------
__global__ __launch_bounds__(256) void sgemm_tn(const float* __restrict__ A,
                                                const float* __restrict__ B,
                                                float* __restrict__ C,
                                                int M, int N, int K) {
    const int BM = 128, BN = 128, BK = 8;
    __shared__ float As[BK][BM];
    __shared__ float Bs[BK][BN];

    int tid = threadIdx.x;
    int m0 = blockIdx.y * BM;
    int n0 = blockIdx.x * BN;

    int lrow = tid >> 1;
    int lcol = (tid & 1) << 2;
    const float* Ap = A + (size_t)(m0 + lrow) * K + lcol;
    const float* Bp = B + (size_t)(n0 + lrow) * K + lcol;

    int ty = tid >> 4;
    int tx = tid & 15;

    float acc[8][8] = {};

    for (int k0 = 0; k0 < K; k0 += BK) {
        float4 a4 = *(const float4*)(Ap + k0);
        float4 b4 = *(const float4*)(Bp + k0);
        As[lcol + 0][lrow] = a4.x; As[lcol + 1][lrow] = a4.y;
        As[lcol + 2][lrow] = a4.z; As[lcol + 3][lrow] = a4.w;
        Bs[lcol + 0][lrow] = b4.x; Bs[lcol + 1][lrow] = b4.y;
        Bs[lcol + 2][lrow] = b4.z; Bs[lcol + 3][lrow] = b4.w;
        __syncthreads();

        #pragma unroll
        for (int kk = 0; kk < BK; kk++) {
            float4 ra0 = *(const float4*)&As[kk][ty * 8];
            float4 ra1 = *(const float4*)&As[kk][ty * 8 + 4];
            float4 rb0 = *(const float4*)&Bs[kk][tx * 8];
            float4 rb1 = *(const float4*)&Bs[kk][tx * 8 + 4];
            float ra[8] = {ra0.x, ra0.y, ra0.z, ra0.w, ra1.x, ra1.y, ra1.z, ra1.w};
            float rb[8] = {rb0.x, rb0.y, rb0.z, rb0.w, rb1.x, rb1.y, rb1.z, rb1.w};
            #pragma unroll
            for (int a = 0; a < 8; a++)
                #pragma unroll
                for (int b = 0; b < 8; b++)
                    acc[a][b] = fmaf(ra[a], rb[b], acc[a][b]);
        }
        __syncthreads();
    }

    #pragma unroll
    for (int a = 0; a < 8; a++) {
        float* crow = C + (size_t)(m0 + ty * 8 + a) * N + n0 + tx * 8;
        float4 v0 = {acc[a][0], acc[a][1], acc[a][2], acc[a][3]};
        float4 v1 = {acc[a][4], acc[a][5], acc[a][6], acc[a][7]};
        *(float4*)(crow) = v0;
        *(float4*)(crow + 4) = v1;
    }
}

// ---------------------------------------------------------------------------
// RoPE + head-split + bf16 hi/lo pre-split:
// qkv[s][3*1024] -> g_{Q,K,V}{h,l} [h][s][64]. Q pre-scaled by 1/8.
// ---------------------------------------------------------------------------
__global__ void rope_kernel(const float* __restrict__ qkv,
                            const int* __restrict__ tpos) {
    int idx = blockIdx.x * blockDim.x + threadIdx.x;
    const int TOTAL = SEQ * NH * (HS / 2);
    if (idx >= TOTAL) return;

    int j = idx & 31;
    int h = (idx >> 5) & (NH - 1);
    int s = idx >> 9;

    float p = (float)tpos[s];
    float invf = (float)(pow(10000.0, -(double)(2 * j) / 64.0));
    float ang = p * invf;
    float cs = cosf(ang);
    float sn = sinf(ang);

    size_t base = (size_t)s * (3 * DM) + h * HS + 2 * j;
    size_t ob = (size_t)h * SEQ * HS + (size_t)s * HS + 2 * j;

    const float SCALE = 0.125f;
    uint32_t hi, lo;

    float q1 = qkv[base], q2 = qkv[base + 1];
    split2((q1 * cs - q2 * sn) * SCALE, (q2 * cs + q1 * sn) * SCALE, hi, lo);
    *(uint32_t*)(g_Qh + ob) = hi;
    *(uint32_t*)(g_Ql + ob) = lo;

    float k1 = qkv[base + DM], k2 = qkv[base + DM + 1];
    split2(k1 * cs - k2 * sn, k2 * cs + k1 * sn, hi, lo);
    *(uint32_t*)(g_Kh + ob) = hi;
    *(uint32_t*)(g_Kl + ob) = lo;

    split2(qkv[base + 2 * DM], qkv[base + 2 * DM + 1], hi, lo);
    *(uint32_t*)(g_Vh + ob) = hi;
    *(uint32_t*)(g_Vl + ob) = lo;
}

// ---------------------------------------------------------------------------
extern "C" void kernel_launch(void* const* d_in, const int* in_sizes, int n_in,
                              void* d_out, int out_size) {
    const float* x    = (const float*)d_in[0];
    const int*   tpos = (const int*)d_in[1];
    const float* wqkv = (const float*)d_in[2];
    const float* wo   = (const float*)d_in[3];
    float* out = (float*)d_out;

    float *qkv_p, *attn_p;
    cudaGetSymbolAddress((void**)&qkv_p, g_qkv);
    cudaGetSymbolAddress((void**)&attn_p, g_attn);

    // 1) QKV projection: [4096,1024] x [3072,1024]^T -> [4096,3072]
    sgemm_tn<<<dim3(3 * DM / 128, SEQ / 128), 256>>>(x, wqkv, qkv_p, SEQ, 3 * DM, DM);

    // 2) RoPE + head split + bf16 hi/lo pre-split
    rope_kernel<<<(SEQ * NH * (HS / 2) + 255) / 256, 256>>>(qkv_p, tpos);

    // 3) Causal flash attention (mma.sync bf16x3, best-known R11 structure)
    cudaFuncSetAttribute(flash_mma, cudaFuncAttributeMaxDynamicSharedMemorySize, FLASH_SMEM);
    flash_mma<<<dim3(SEQ / 128, NH), 256, FLASH_SMEM>>>();

    // 4) Output projection: [4096,1024] x [1024,1024]^T -> [4096,1024]
    sgemm_tn<<<dim3(DM / 128, SEQ / 128), 256>>>(attn_p, wo, out, SEQ, DM, DM);
}